// round 7
// baseline (speedup 1.0000x reference)
#include <cuda_runtime.h>
#include <math.h>

// Problem shapes (fixed by the dataset)
#define Bn 8192
#define En 256
#define Cn 25

// Tile config for the distance GEMM
#define BM 128
#define BN 128
#define BK 8
#define NB (Bn / BM)                 // 64 block-rows
#define NTRI (NB * (NB + 1) / 2)     // 2080 triangular blocks

// Packed fp32x2 helpers (Blackwell sm_10x; 2 independent IEEE fp32 ops/instr)
#define FMA_F32X2(d, a, b, c) \
    asm("fma.rn.f32x2 %0, %1, %2, %3;" : "=l"(d) : "l"(a), "l"(b), "l"(c))
#define PACK_F32X2_DUP(out, x) \
    asm("mov.b64 %0, {%1, %1};" : "=l"(out) : "r"(__float_as_uint(x)))
#define UNPACK_F32X2(lo, hi, in) \
    asm("mov.b64 {%0, %1}, %2;" : "=r"(lo), "=r"(hi) : "l"(in))

// Scratch (static __device__ globals — allocation-free per harness rules)
__device__ float g_D[(size_t)Bn * Bn];   // 256 MB distance matrix
__device__ float g_sq[Bn];
__device__ int   g_labels[Bn];

// ---------------------------------------------------------------------------
// Kernel 1: squared norms + argmax cluster labels. One warp per row.
// ---------------------------------------------------------------------------
__global__ void prep_kernel(const float* __restrict__ X, const float* __restrict__ cat) {
    int warp = (blockIdx.x * blockDim.x + threadIdx.x) >> 5;
    int lane = threadIdx.x & 31;
    if (warp >= Bn) return;

    const float* xr = X + (size_t)warp * En;
    float s = 0.f;
#pragma unroll
    for (int c = lane; c < En; c += 32) { float v = xr[c]; s = fmaf(v, v, s); }
#pragma unroll
    for (int o = 16; o; o >>= 1) s += __shfl_xor_sync(0xffffffffu, s, o);

    const float* cr = cat + (size_t)warp * Cn;
    float bv = (lane < Cn) ? cr[lane] : -3.4e38f;
    int   bi = lane;
#pragma unroll
    for (int o = 16; o; o >>= 1) {
        float ov = __shfl_xor_sync(0xffffffffu, bv, o);
        int   oi = __shfl_xor_sync(0xffffffffu, bi, o);
        if (ov > bv || (ov == bv && oi < bi)) { bv = ov; bi = oi; }
    }
    if (lane == 0) { g_sq[warp] = s; g_labels[warp] = bi; }
}

// ---------------------------------------------------------------------------
// Kernel 2: symmetric distance GEMM, 128x128x8 double-buffered, 8x8/thread,
// inner product done with packed fp32x2 FFMA (2 fp32 FMA per instruction).
// 1D triangular grid: block t -> (bi, bj) with bi <= bj (no dead blocks).
// Off-diagonal blocks also write the mirrored (j,i) tile through a 32-row
// smem transpose stage so both global writes stay coalesced.
// ---------------------------------------------------------------------------
__global__ void __launch_bounds__(256)
dist_kernel(const float* __restrict__ X) {
    // triangular decode: row bi has (NB - bi) blocks; offset f(i) = i*(2*NB+1-i)/2
    int t = blockIdx.x;
    int bi = (int)(((float)(2 * NB + 1) -
                    sqrtf((float)(2 * NB + 1) * (2 * NB + 1) - 8.0f * (float)t)) * 0.5f);
    // integer fix-up against float rounding
    while (bi > 0 && bi * (2 * NB + 1 - bi) / 2 > t) bi--;
    while ((bi + 1) * (2 * NB + 1 - (bi + 1)) / 2 <= t) bi++;
    int bj = bi + (t - bi * (2 * NB + 1 - bi) / 2);

    __shared__ __align__(16) float As[2][BK][BM + 4];
    __shared__ __align__(16) float Bs[2][BK][BN + 4];
    __shared__ __align__(16) float stage[32][BM + 1];

    int tid = threadIdx.x;           // 256 threads
    int tx = tid & 15, ty = tid >> 4;
    int row0 = bi * BM, col0 = bj * BN;

    // global->smem load indices: 128 rows x 8 k = 1024 floats = 256 x float4
    int lr = tid >> 1;               // 0..127 tile row
    int lk = (tid & 1) * 4;          // 0 or 4

    const float* Ag = X + (size_t)(row0 + lr) * En + lk;
    const float* Bg = X + (size_t)(col0 + lr) * En + lk;

    // accumulators: [q][pp] = f32x2 pair (col 2*pp, col 2*pp+1)
    unsigned long long acc2[8][4];
#pragma unroll
    for (int q = 0; q < 8; q++)
#pragma unroll
        for (int pp = 0; pp < 4; pp++) acc2[q][pp] = 0ull;

    // preload k-tile 0
    {
        float4 av = *(const float4*)(Ag);
        float4 bv = *(const float4*)(Bg);
        As[0][lk + 0][lr] = av.x; As[0][lk + 1][lr] = av.y;
        As[0][lk + 2][lr] = av.z; As[0][lk + 3][lr] = av.w;
        Bs[0][lk + 0][lr] = bv.x; Bs[0][lk + 1][lr] = bv.y;
        Bs[0][lk + 2][lr] = bv.z; Bs[0][lk + 3][lr] = bv.w;
    }
    __syncthreads();

    for (int k0 = 0; k0 < En; k0 += BK) {
        int buf = (k0 / BK) & 1;
        float4 pa, pb;
        bool more = (k0 + BK) < En;
        if (more) {
            pa = *(const float4*)(Ag + k0 + BK);
            pb = *(const float4*)(Bg + k0 + BK);
        }
#pragma unroll
        for (int kk = 0; kk < BK; kk++) {
            float a[8];
            *(float4*)(a + 0) = *(const float4*)(&As[buf][kk][ty * 8 + 0]);
            *(float4*)(a + 4) = *(const float4*)(&As[buf][kk][ty * 8 + 4]);
            // B fragment loaded directly as 4 packed f32x2 (same LDS.128s)
            unsigned long long b2[4];
            {
                ulonglong2 u0 = *(const ulonglong2*)(&Bs[buf][kk][tx * 8 + 0]);
                ulonglong2 u1 = *(const ulonglong2*)(&Bs[buf][kk][tx * 8 + 4]);
                b2[0] = u0.x; b2[1] = u0.y; b2[2] = u1.x; b2[3] = u1.y;
            }
#pragma unroll
            for (int q = 0; q < 8; q++) {
                unsigned long long aq;
                PACK_F32X2_DUP(aq, a[q]);
#pragma unroll
                for (int pp = 0; pp < 4; pp++)
                    FMA_F32X2(acc2[q][pp], aq, b2[pp], acc2[q][pp]);
            }
        }
        if (more) {
            int nb = buf ^ 1;
            As[nb][lk + 0][lr] = pa.x; As[nb][lk + 1][lr] = pa.y;
            As[nb][lk + 2][lr] = pa.z; As[nb][lk + 3][lr] = pa.w;
            Bs[nb][lk + 0][lr] = pb.x; Bs[nb][lk + 1][lr] = pb.y;
            Bs[nb][lk + 2][lr] = pb.z; Bs[nb][lk + 3][lr] = pb.w;
        }
        __syncthreads();
    }

    // Unpack accumulators, then transform to distances IN PLACE
    float acc[8][8];
#pragma unroll
    for (int q = 0; q < 8; q++)
#pragma unroll
        for (int pp = 0; pp < 4; pp++) {
            unsigned lo, hi;
            UNPACK_F32X2(lo, hi, acc2[q][pp]);
            acc[q][2 * pp + 0] = __uint_as_float(lo);
            acc[q][2 * pp + 1] = __uint_as_float(hi);
        }

    float si[8], sj[8];
#pragma unroll
    for (int q = 0; q < 8; q++) si[q] = g_sq[row0 + ty * 8 + q];
#pragma unroll
    for (int p = 0; p < 8; p++) sj[p] = g_sq[col0 + tx * 8 + p];
#pragma unroll
    for (int q = 0; q < 8; q++)
#pragma unroll
        for (int p = 0; p < 8; p++) {
            float d2 = si[q] + sj[p] - 2.f * acc[q][p];
            acc[q][p] = sqrtf(fmaxf(d2, 0.f));
        }

    // Direct (i,j) tile write: coalesced float4
#pragma unroll
    for (int q = 0; q < 8; q++) {
        float* dst = g_D + (size_t)(row0 + ty * 8 + q) * Bn + col0 + tx * 8;
        *(float4*)(dst + 0) = make_float4(acc[q][0], acc[q][1], acc[q][2], acc[q][3]);
        *(float4*)(dst + 4) = make_float4(acc[q][4], acc[q][5], acc[q][6], acc[q][7]);
    }

    // Mirrored (j,i) tile via 32-row smem transpose chunks (coalesced rows)
    if (bi != bj) {
#pragma unroll
        for (int chunk = 0; chunk < 4; chunk++) {
            __syncthreads();
            if ((tx >> 2) == chunk) {
#pragma unroll
                for (int p = 0; p < 8; p++)
#pragma unroll
                    for (int q = 0; q < 8; q++)
                        stage[(tx & 3) * 8 + p][ty * 8 + q] = acc[q][p];
            }
            __syncthreads();
#pragma unroll
            for (int it = 0; it < 16; it++) {
                int idx = it * 256 + tid;
                int r = idx >> 7, c = idx & 127;
                g_D[(size_t)(col0 + chunk * 32 + r) * Bn + row0 + c] = stage[r][c];
            }
        }
    }
}

// ---------------------------------------------------------------------------
// Kernel 3: per-row exact (k+1)-th smallest via radix bit-search on float
// bits (nonnegative floats order-isomorphic to uint32), then strict-< label
// histogram + entropy. One block (256 threads) per row; row register-resident.
// Radix loop uses ONE barrier per iteration: warp counts go to a double-
// buffered s_warp[bit&1][8]; every thread sums all 8 redundantly, so the
// predicate decision is uniform without a broadcast barrier.
// ---------------------------------------------------------------------------
__global__ void select_entropy_kernel(const int* __restrict__ kptr,
                                      float* __restrict__ out_e) {
    int row = blockIdx.x;
    int tid = threadIdx.x;
    int wid = tid >> 5, lane = tid & 31;
    const float* drow = g_D + (size_t)row * Bn;

    unsigned v[32];
#pragma unroll
    for (int s = 0; s < 32; s++)
        v[s] = __float_as_uint(drow[s * 256 + tid]);

    int k = kptr ? *kptr : 15;
    if (k < 0) k = 0;
    if (k > 255) k = 255;            // defensive clamp; real input is 15

    __shared__ int s_warp[2][8];

    // Find the largest u with count_less(u) <= k  ==>  u = bits of sorted[k]
    unsigned prefix = 0u;
#pragma unroll 1
    for (int bit = 30; bit >= 0; bit--) {
        int b = bit & 1;
        unsigned cand = prefix | (1u << bit);
        int c = 0;
#pragma unroll
        for (int s = 0; s < 32; s++) c += (v[s] < cand) ? 1 : 0;
#pragma unroll
        for (int o = 16; o; o >>= 1) c += __shfl_xor_sync(0xffffffffu, c, o);
        if (lane == 0) s_warp[b][wid] = c;
        __syncthreads();
        int tot = 0;
#pragma unroll
        for (int w = 0; w < 8; w++) tot += s_warp[b][w];
        if (tot <= k) prefix = cand;
        // WAR safety: buffer b is re-written two iterations later, strictly
        // after the intervening iteration's __syncthreads().
    }

    // Strict-< histogram of neighbour labels (only ~k hits total)
    __shared__ int cnts[32];
    __syncthreads();                 // all reads of s_warp done before reuse below
    if (tid < 32) cnts[tid] = 0;
    __syncthreads();
#pragma unroll
    for (int s = 0; s < 32; s++) {
        if (v[s] < prefix) {
            int j = s * 256 + tid;
            atomicAdd(&cnts[g_labels[j]], 1);
        }
    }
    __syncthreads();

    if (tid < 32) {
        int cv = (tid < Cn) ? cnts[tid] : 0;
        int n = cv;
#pragma unroll
        for (int o = 16; o; o >>= 1) n += __shfl_xor_sync(0xffffffffu, n, o);
        float rn = 1.0f / (float)max(n, 1);
        float b = (float)cv * rn;
        float term = (tid < Cn) ? b * logf(b + 1e-5f) : 0.f;
#pragma unroll
        for (int o = 16; o; o >>= 1) term += __shfl_xor_sync(0xffffffffu, term, o);
        if (tid == 0) out_e[row] = -term;
    }
}

// ---------------------------------------------------------------------------
// Kernel 4: identity copy encodings -> out (graph-capturable, vectorized)
// ---------------------------------------------------------------------------
__global__ void copy_kernel(const float4* __restrict__ src, float4* __restrict__ dst, int n) {
    int i = blockIdx.x * blockDim.x + threadIdx.x;
    if (i < n) dst[i] = src[i];
}

extern "C" void kernel_launch(void* const* d_in, const int* in_sizes, int n_in,
                              void* d_out, int out_size) {
    const float* X   = (const float*)d_in[0];
    const float* cat = (const float*)d_in[1];
    const int* kptr  = (n_in >= 3) ? (const int*)d_in[2] : nullptr;
    float* out = (float*)d_out;

    float* out_e = nullptr;
    bool do_copy = false;

    if (out_size == Bn * En + Bn) {          // (encodings, entropy) concatenated
        do_copy = true;
        out_e = out + (size_t)Bn * En;
    } else if (out_size == Bn) {             // entropy only
        out_e = out;
    } else if (out_size == Bn * En) {        // encodings only (identity)
        do_copy = true;
    } else {                                  // fallback: assume concat if it fits
        do_copy = true;
        if (out_size >= Bn * En + Bn) out_e = out + (size_t)Bn * En;
    }

    if (do_copy) {
        int n4 = Bn * En / 4;
        copy_kernel<<<(n4 + 255) / 256, 256>>>((const float4*)X, (float4*)out, n4);
    }

    prep_kernel<<<Bn / 8, 256>>>(X, cat);

    dist_kernel<<<NTRI, 256>>>(X);

    if (out_e) select_entropy_kernel<<<Bn, 256>>>(kptr, out_e);
}